// round 15
// baseline (speedup 1.0000x reference)
#include <cuda_runtime.h>
#include <cuda_bf16.h>
#include <cstdint>

// Problem dims (fixed)
#define BATCH 64
#define CIN   512
#define TLEN  1024
#define COUT  256

// GEMM tiling
#define KC      32                 // channels per k-chunk
#define NCHUNK  (CIN/KC)           // 16
#define ROWB    80                 // smem row pitch bytes (32 bf16 = 64B + 16B pad)
#define TILEB   (128*ROWB)         // 10240 B per part tile (128 rows)
#define ABASE   0                  // A parts at dsm+0 (3 tiles)
#define BBASE   (3*TILEB)          // B parts at dsm+30720 (3 tiles)
#define DSMB    (6*TILEB)          // 61440 B dynamic smem

// 64 MiB intermediate y in [B][T][COUT] (o contiguous -> coalesced LIF reads)
__device__ float g_y[(size_t)BATCH * TLEN * COUT];
// Pre-split, pre-tiled W parts: [(ot*16+kc)*3+p] tiles, each the exact smem image
__device__ __align__(16) unsigned char g_Wt[2 * NCHUNK * 3 * TILEB];

// ---------------------------------------------------------------------------
// 3-way bf16 split: x ~= h + m + l (residuals exact in fp32)
__device__ __forceinline__ void split3(float x, __nv_bfloat16& h,
                                       __nv_bfloat16& m, __nv_bfloat16& l) {
    h = __float2bfloat16(x);
    float r = x - __bfloat162float(h);
    m = __float2bfloat16(r);
    l = __float2bfloat16(r - __bfloat162float(m));
}
__device__ __forceinline__ uint32_t pack2(__nv_bfloat16 a, __nv_bfloat16 b) {
    __nv_bfloat162 v; v.x = a; v.y = b;
    return *reinterpret_cast<uint32_t*>(&v);
}
// m16n8k16 row.col bf16 -> f32 accumulate (sm_80 feature; legal on compute_103)
__device__ __forceinline__ void mma16816(float* d, const uint32_t* a,
                                         const uint32_t* b) {
    asm volatile(
        "mma.sync.aligned.m16n8k16.row.col.f32.bf16.bf16.f32 "
        "{%0,%1,%2,%3}, {%4,%5,%6,%7}, {%8,%9}, {%0,%1,%2,%3};\n"
        : "+f"(d[0]), "+f"(d[1]), "+f"(d[2]), "+f"(d[3])
        : "r"(a[0]), "r"(a[1]), "r"(a[2]), "r"(a[3]), "r"(b[0]), "r"(b[1]));
}

// ============================================================================
// Kernel 0: split W into 3 bf16 part tiles laid out as exact smem images.
// One thread per (tile, o-row, c4-group of 4 channels).  98304 threads.
// ============================================================================
__global__ __launch_bounds__(256) void wprep_kernel(const float* __restrict__ W)
{
    int g  = blockIdx.x * 256 + threadIdx.x;   // 0..98303
    int c4 = g & 7;
    int o  = (g >> 3) & 127;
    int ti = g >> 10;                          // 0..95 = (ot*16+kc)*3+p
    int p  = ti % 3;
    int q  = ti / 3;
    int kc = q & 15;
    int ot = q >> 4;

    float4 wv = *(const float4*)(W + (size_t)(ot * 128 + o) * CIN + kc * KC + c4 * 4);

    float vv[4] = {wv.x, wv.y, wv.z, wv.w};
    __nv_bfloat16 part[4];
#pragma unroll
    for (int j = 0; j < 4; j++) {
        __nv_bfloat16 h, m, l;
        split3(vv[j], h, m, l);
        part[j] = (p == 0) ? h : (p == 1) ? m : l;
    }
    *reinterpret_cast<uint2*>(g_Wt + (size_t)ti * TILEB + o * ROWB + c4 * 8) =
        make_uint2(pack2(part[0], part[1]), pack2(part[2], part[3]));
}

// ============================================================================
// Kernel 1: split-bf16 HMMA GEMM + BN -> g_y[b][t][o]
//   D[o][t] = sum_{(p,q): p+q<=2} sum_c Wp[o][c] * xq[c][t]
// grid (8 t-tiles, 2 o-tiles, 64 b), 256 thr, warps 2(o)x4(t), 64x32/warp.
// ============================================================================
__global__ __launch_bounds__(256, 2) void gemm_mma_kernel(
    const float* __restrict__ x,
    const float* __restrict__ gamma, const float* __restrict__ beta,
    const float* __restrict__ rmean, const float* __restrict__ rvar)
{
    extern __shared__ __align__(16) char dsm[];

    const int tid    = threadIdx.x;
    const int wid    = tid >> 5;
    const int lane   = tid & 31;
    const int grp    = lane >> 2;     // 0..7
    const int t4     = lane & 3;      // 0..3
    const int warp_o = wid >> 2;      // 0..1
    const int warp_t = wid & 3;       // 0..3

    const int tBase = blockIdx.x * 128;
    const int ot    = blockIdx.y;
    const int oBase = ot * 128;
    const int b     = blockIdx.z;

    const float* xb = x + (size_t)b * CIN * TLEN + tBase;

    float acc[4][4][4];
#pragma unroll
    for (int mi = 0; mi < 4; mi++)
#pragma unroll
        for (int ni = 0; ni < 4; ni++)
#pragma unroll
            for (int r = 0; r < 4; r++) acc[mi][ni][r] = 0.0f;

    // per-thread fragment byte offsets (conflict-free by the pitch-80 trick)
    const int aoff = (warp_o * 64 + grp) * ROWB + t4 * 4;
    const int boff = (warp_t * 32 + grp) * ROWB + t4 * 4;

    for (int kc = 0; kc < NCHUNK; kc++) {
        __syncthreads();   // smem free from previous chunk's mma reads

        // ---- A: copy pre-built part tiles (30720 B, L2-resident) -----------
        {
            const uint4* src = (const uint4*)(g_Wt + (size_t)((ot * NCHUNK + kc) * 3) * TILEB);
            uint4* dst = (uint4*)dsm;
            for (int i = tid; i < 3 * TILEB / 16; i += 256) dst[i] = src[i];
        }
        // ---- B: load x chunk, 3-way split, transpose to [t][k] rows --------
#pragma unroll
        for (int i = 0; i < 4; i++) {
            int pos = tid + 256 * i;          // 0..1023
            int t  = pos & 127;
            int c4 = pos >> 7;                // 0..7
            const float* xp = xb + (size_t)(kc * KC + c4 * 4) * TLEN + t;
            float v0 = xp[0 * TLEN], v1 = xp[1 * TLEN];
            float v2 = xp[2 * TLEN], v3 = xp[3 * TLEN];
            __nv_bfloat16 h[4], m[4], l[4];
            split3(v0, h[0], m[0], l[0]);
            split3(v1, h[1], m[1], l[1]);
            split3(v2, h[2], m[2], l[2]);
            split3(v3, h[3], m[3], l[3]);
            char* bp = dsm + BBASE + t * ROWB + c4 * 8;
            *(uint2*)(bp)             = make_uint2(pack2(h[0], h[1]), pack2(h[2], h[3]));
            *(uint2*)(bp + TILEB)     = make_uint2(pack2(m[0], m[1]), pack2(m[2], m[3]));
            *(uint2*)(bp + 2 * TILEB) = make_uint2(pack2(l[0], l[1]), pack2(l[2], l[3]));
        }
        __syncthreads();

        // ---- 6 part-pairs x 2 k16-steps of HMMA ----------------------------
        const int PP[6] = {0, 0, 1, 0, 1, 2};
        const int QQ[6] = {0, 1, 0, 2, 1, 0};
#pragma unroll
        for (int pi = 0; pi < 6; pi++) {
            const char* Ap = dsm + PP[pi] * TILEB + aoff;
            const char* Bp = dsm + BBASE + QQ[pi] * TILEB + boff;
#pragma unroll
            for (int ks = 0; ks < 2; ks++) {
                uint32_t afr[4][4], bfr[4][2];
#pragma unroll
                for (int mi = 0; mi < 4; mi++) {
                    const char* ab = Ap + mi * (16 * ROWB) + ks * 32;
                    afr[mi][0] = *(const uint32_t*)(ab);
                    afr[mi][1] = *(const uint32_t*)(ab + 8 * ROWB);
                    afr[mi][2] = *(const uint32_t*)(ab + 16);
                    afr[mi][3] = *(const uint32_t*)(ab + 8 * ROWB + 16);
                }
#pragma unroll
                for (int ni = 0; ni < 4; ni++) {
                    const char* bb = Bp + ni * (8 * ROWB) + ks * 32;
                    bfr[ni][0] = *(const uint32_t*)(bb);
                    bfr[ni][1] = *(const uint32_t*)(bb + 16);
                }
#pragma unroll
                for (int mi = 0; mi < 4; mi++)
#pragma unroll
                    for (int ni = 0; ni < 4; ni++)
                        mma16816(acc[mi][ni], afr[mi], bfr[ni]);
            }
        }
    }

    // ---- epilogue: BN + transpose via smem, coalesced float4 stores --------
    float* se = (float*)dsm;   // [t 128][o 68 pitch] fp32, 34816 B
#pragma unroll
    for (int h = 0; h < 2; h++) {
        __syncthreads();
        if (warp_o == h) {
#pragma unroll
            for (int mi = 0; mi < 4; mi++) {
                // BN coeffs for this thread's two o-rows of tile mi
                float sc0, sh0, sc1, sh1;
                {
                    int o0 = oBase + h * 64 + mi * 16 + grp;
                    int o1 = o0 + 8;
                    sc0 = gamma[o0] * rsqrtf(rvar[o0] + 1e-5f);
                    sh0 = beta[o0] - rmean[o0] * sc0;
                    sc1 = gamma[o1] * rsqrtf(rvar[o1] + 1e-5f);
                    sh1 = beta[o1] - rmean[o1] * sc1;
                }
#pragma unroll
                for (int ni = 0; ni < 4; ni++) {
                    int tc = warp_t * 32 + ni * 8 + 2 * t4;
                    int oc = mi * 16 + grp;
                    se[(tc    ) * 68 + oc    ] = fmaf(acc[mi][ni][0], sc0, sh0);
                    se[(tc + 1) * 68 + oc    ] = fmaf(acc[mi][ni][1], sc0, sh0);
                    se[(tc    ) * 68 + oc + 8] = fmaf(acc[mi][ni][2], sc1, sh1);
                    se[(tc + 1) * 68 + oc + 8] = fmaf(acc[mi][ni][3], sc1, sh1);
                }
            }
        }
        __syncthreads();
        // cooperative coalesced store of the 128t x 64o half
#pragma unroll
        for (int i = 0; i < 8; i++) {
            int idx = tid + 256 * i;        // 0..2047
            int o4  = idx & 15;
            int t   = idx >> 4;
            float4 v = *(const float4*)(se + t * 68 + o4 * 4);
            *(float4*)(g_y + ((size_t)(b * TLEN + tBase + t)) * COUT
                       + oBase + h * 64 + o4 * 4) = v;
        }
    }
}

// ============================================================================
// Kernel 2: LIF recurrence + time-mean, 4-deep chunk pipeline (48 loads live).
// ============================================================================
__global__ __launch_bounds__(128) void lif_kernel(float* __restrict__ out)
{
    const int idx = blockIdx.x * 128 + threadIdx.x;   // 0..16383
    const int b = idx >> 8;
    const int o = idx & 255;
    const float* p = g_y + (size_t)b * TLEN * COUT + o;

    float B0[16], B1[16], B2[16], B3[16];
    float v = 0.0f, sum = 0.0f;

#define LOADC(BUF, c) do {                                                    \
    const float* _q = p + (size_t)(c) * 16 * COUT;                            \
    _Pragma("unroll")                                                         \
    for (int j = 0; j < 16; j++) BUF[j] = _q[(size_t)j * COUT];               \
} while (0)
#define PROC(BUF) do {                                                        \
    _Pragma("unroll")                                                         \
    for (int j = 0; j < 16; j++) {                                            \
        float u = v + (BUF[j] - v) * 0.5f;   /* exact: (y-v)/TAU, TAU=2 */    \
        bool sp = (u >= 1.0f);                                                \
        sum += sp ? 1.0f : 0.0f;                                              \
        v = sp ? 0.0f : u;                                                    \
    }                                                                         \
} while (0)

    LOADC(B0, 0); LOADC(B1, 1); LOADC(B2, 2);
#pragma unroll 1
    for (int i = 0; i < 60; i += 4) {
        LOADC(B3, i + 3); PROC(B0);
        LOADC(B0, i + 4); PROC(B1);
        LOADC(B1, i + 5); PROC(B2);
        LOADC(B2, i + 6); PROC(B3);
    }
    LOADC(B3, 63);
    PROC(B0); PROC(B1); PROC(B2); PROC(B3);

    out[idx] = sum * (1.0f / 1024.0f);
#undef LOADC
#undef PROC
}

// ============================================================================
extern "C" void kernel_launch(void* const* d_in, const int* in_sizes, int n_in,
                              void* d_out, int out_size)
{
    const float* x     = (const float*)d_in[0];
    const float* W     = (const float*)d_in[1];
    const float* gamma = (const float*)d_in[2];
    const float* beta  = (const float*)d_in[3];
    const float* rmean = (const float*)d_in[4];
    const float* rvar  = (const float*)d_in[5];
    float* out = (float*)d_out;

    cudaFuncSetAttribute(gemm_mma_kernel,
                         cudaFuncAttributeMaxDynamicSharedMemorySize, DSMB);

    wprep_kernel<<<384, 256>>>(W);

    dim3 g1(TLEN / 128, COUT / 128, BATCH);   // 8 x 2 x 64 = 1024 blocks
    gemm_mma_kernel<<<g1, 256, DSMB>>>(x, gamma, beta, rmean, rvar);

    lif_kernel<<<(BATCH * COUT) / 128, 128>>>(out);
}

// round 16
// speedup vs baseline: 1.0058x; 1.0058x over previous
#include <cuda_runtime.h>
#include <cuda_bf16.h>
#include <cstdint>

// Problem dims (fixed)
#define BATCH 64
#define CIN   512
#define TLEN  1024
#define COUT  256

// GEMM tiling
#define KC      32                 // channels per k-chunk
#define NCHUNK  (CIN/KC)           // 16
#define ROWB    80                 // smem row pitch bytes (32 bf16 = 64B + 16B pad)
#define TILEB   (128*ROWB)         // 10240 B per part tile (128 rows)
#define ABASE   0                  // A parts at dsm+0 (3 tiles)
#define BBASE   (3*TILEB)          // B parts at dsm+30720 (3 tiles)
#define DSMB    (6*TILEB)          // 61440 B dynamic smem

// 64 MiB intermediate y in [B][T][COUT] (o contiguous -> coalesced LIF reads)
__device__ float g_y[(size_t)BATCH * TLEN * COUT];
// Pre-split, pre-tiled W parts: [(ot*16+kc)*3+p] tiles, each the exact smem image
__device__ __align__(16) unsigned char g_Wt[2 * NCHUNK * 3 * TILEB];

// ---------------------------------------------------------------------------
// 3-way bf16 split: x ~= h + m + l (residuals exact in fp32)
__device__ __forceinline__ void split3(float x, __nv_bfloat16& h,
                                       __nv_bfloat16& m, __nv_bfloat16& l) {
    h = __float2bfloat16(x);
    float r = x - __bfloat162float(h);
    m = __float2bfloat16(r);
    l = __float2bfloat16(r - __bfloat162float(m));
}
__device__ __forceinline__ uint32_t pack2(__nv_bfloat16 a, __nv_bfloat16 b) {
    __nv_bfloat162 v; v.x = a; v.y = b;
    return *reinterpret_cast<uint32_t*>(&v);
}
// m16n8k16 row.col bf16 -> f32 accumulate (sm_80 feature; legal on compute_103)
__device__ __forceinline__ void mma16816(float* d, const uint32_t* a,
                                         const uint32_t* b) {
    asm volatile(
        "mma.sync.aligned.m16n8k16.row.col.f32.bf16.bf16.f32 "
        "{%0,%1,%2,%3}, {%4,%5,%6,%7}, {%8,%9}, {%0,%1,%2,%3};\n"
        : "+f"(d[0]), "+f"(d[1]), "+f"(d[2]), "+f"(d[3])
        : "r"(a[0]), "r"(a[1]), "r"(a[2]), "r"(a[3]), "r"(b[0]), "r"(b[1]));
}

// ============================================================================
// Kernel 0: split W into 3 bf16 part tiles laid out as exact smem images.
// One thread per (tile, o-row, c4-group of 4 channels).  98304 threads.
// ============================================================================
__global__ __launch_bounds__(256) void wprep_kernel(const float* __restrict__ W)
{
    int g  = blockIdx.x * 256 + threadIdx.x;   // 0..98303
    int c4 = g & 7;
    int o  = (g >> 3) & 127;
    int ti = g >> 10;                          // 0..95 = (ot*16+kc)*3+p
    int p  = ti % 3;
    int q  = ti / 3;
    int kc = q & 15;
    int ot = q >> 4;

    float4 wv = *(const float4*)(W + (size_t)(ot * 128 + o) * CIN + kc * KC + c4 * 4);

    float vv[4] = {wv.x, wv.y, wv.z, wv.w};
    __nv_bfloat16 part[4];
#pragma unroll
    for (int j = 0; j < 4; j++) {
        __nv_bfloat16 h, m, l;
        split3(vv[j], h, m, l);
        part[j] = (p == 0) ? h : (p == 1) ? m : l;
    }
    *reinterpret_cast<uint2*>(g_Wt + (size_t)ti * TILEB + o * ROWB + c4 * 8) =
        make_uint2(pack2(part[0], part[1]), pack2(part[2], part[3]));
}

// ============================================================================
// Kernel 1: split-bf16 HMMA GEMM + BN -> g_y[b][t][o]
//   D[o][t] = sum_{(p,q): p+q<=2} sum_c Wp[o][c] * xq[c][t]
// grid (8 t-tiles, 2 o-tiles, 64 b), 256 thr, warps 2(o)x4(t), 64x32/warp.
// ============================================================================
__global__ __launch_bounds__(256, 2) void gemm_mma_kernel(
    const float* __restrict__ x,
    const float* __restrict__ gamma, const float* __restrict__ beta,
    const float* __restrict__ rmean, const float* __restrict__ rvar)
{
    extern __shared__ __align__(16) char dsm[];

    const int tid    = threadIdx.x;
    const int wid    = tid >> 5;
    const int lane   = tid & 31;
    const int grp    = lane >> 2;     // 0..7
    const int t4     = lane & 3;      // 0..3
    const int warp_o = wid >> 2;      // 0..1
    const int warp_t = wid & 3;       // 0..3

    const int tBase = blockIdx.x * 128;
    const int ot    = blockIdx.y;
    const int oBase = ot * 128;
    const int b     = blockIdx.z;

    const float* xb = x + (size_t)b * CIN * TLEN + tBase;

    float acc[4][4][4];
#pragma unroll
    for (int mi = 0; mi < 4; mi++)
#pragma unroll
        for (int ni = 0; ni < 4; ni++)
#pragma unroll
            for (int r = 0; r < 4; r++) acc[mi][ni][r] = 0.0f;

    // per-thread fragment byte offsets (conflict-free by the pitch-80 trick)
    const int aoff = (warp_o * 64 + grp) * ROWB + t4 * 4;
    const int boff = (warp_t * 32 + grp) * ROWB + t4 * 4;

    for (int kc = 0; kc < NCHUNK; kc++) {
        __syncthreads();   // smem free from previous chunk's mma reads

        // ---- A: copy pre-built part tiles (30720 B, L2-resident) -----------
        {
            const uint4* src = (const uint4*)(g_Wt + (size_t)((ot * NCHUNK + kc) * 3) * TILEB);
            uint4* dst = (uint4*)dsm;
            for (int i = tid; i < 3 * TILEB / 16; i += 256) dst[i] = src[i];
        }
        // ---- B: load x chunk, 3-way split, transpose to [t][k] rows --------
#pragma unroll
        for (int i = 0; i < 4; i++) {
            int pos = tid + 256 * i;          // 0..1023
            int t  = pos & 127;
            int c4 = pos >> 7;                // 0..7
            const float* xp = xb + (size_t)(kc * KC + c4 * 4) * TLEN + t;
            float v0 = xp[0 * TLEN], v1 = xp[1 * TLEN];
            float v2 = xp[2 * TLEN], v3 = xp[3 * TLEN];
            __nv_bfloat16 h[4], m[4], l[4];
            split3(v0, h[0], m[0], l[0]);
            split3(v1, h[1], m[1], l[1]);
            split3(v2, h[2], m[2], l[2]);
            split3(v3, h[3], m[3], l[3]);
            char* bp = dsm + BBASE + t * ROWB + c4 * 8;
            *(uint2*)(bp)             = make_uint2(pack2(h[0], h[1]), pack2(h[2], h[3]));
            *(uint2*)(bp + TILEB)     = make_uint2(pack2(m[0], m[1]), pack2(m[2], m[3]));
            *(uint2*)(bp + 2 * TILEB) = make_uint2(pack2(l[0], l[1]), pack2(l[2], l[3]));
        }
        __syncthreads();

        // ---- 6 part-pairs x 2 k16-steps of HMMA ----------------------------
        const int PP[6] = {0, 0, 1, 0, 1, 2};
        const int QQ[6] = {0, 1, 0, 2, 1, 0};
#pragma unroll
        for (int pi = 0; pi < 6; pi++) {
            const char* Ap = dsm + PP[pi] * TILEB + aoff;
            const char* Bp = dsm + BBASE + QQ[pi] * TILEB + boff;
#pragma unroll
            for (int ks = 0; ks < 2; ks++) {
                uint32_t afr[4][4], bfr[4][2];
#pragma unroll
                for (int mi = 0; mi < 4; mi++) {
                    const char* ab = Ap + mi * (16 * ROWB) + ks * 32;
                    afr[mi][0] = *(const uint32_t*)(ab);
                    afr[mi][1] = *(const uint32_t*)(ab + 8 * ROWB);
                    afr[mi][2] = *(const uint32_t*)(ab + 16);
                    afr[mi][3] = *(const uint32_t*)(ab + 8 * ROWB + 16);
                }
#pragma unroll
                for (int ni = 0; ni < 4; ni++) {
                    const char* bb = Bp + ni * (8 * ROWB) + ks * 32;
                    bfr[ni][0] = *(const uint32_t*)(bb);
                    bfr[ni][1] = *(const uint32_t*)(bb + 16);
                }
#pragma unroll
                for (int mi = 0; mi < 4; mi++)
#pragma unroll
                    for (int ni = 0; ni < 4; ni++)
                        mma16816(acc[mi][ni], afr[mi], bfr[ni]);
            }
        }
    }

    // ---- epilogue: BN + transpose via smem, coalesced float4 stores --------
    float* se = (float*)dsm;   // [t 128][o 68 pitch] fp32, 34816 B
#pragma unroll
    for (int h = 0; h < 2; h++) {
        __syncthreads();
        if (warp_o == h) {
#pragma unroll
            for (int mi = 0; mi < 4; mi++) {
                // BN coeffs for this thread's two o-rows of tile mi
                float sc0, sh0, sc1, sh1;
                {
                    int o0 = oBase + h * 64 + mi * 16 + grp;
                    int o1 = o0 + 8;
                    sc0 = gamma[o0] * rsqrtf(rvar[o0] + 1e-5f);
                    sh0 = beta[o0] - rmean[o0] * sc0;
                    sc1 = gamma[o1] * rsqrtf(rvar[o1] + 1e-5f);
                    sh1 = beta[o1] - rmean[o1] * sc1;
                }
#pragma unroll
                for (int ni = 0; ni < 4; ni++) {
                    int tc = warp_t * 32 + ni * 8 + 2 * t4;
                    int oc = mi * 16 + grp;
                    se[(tc    ) * 68 + oc    ] = fmaf(acc[mi][ni][0], sc0, sh0);
                    se[(tc + 1) * 68 + oc    ] = fmaf(acc[mi][ni][1], sc0, sh0);
                    se[(tc    ) * 68 + oc + 8] = fmaf(acc[mi][ni][2], sc1, sh1);
                    se[(tc + 1) * 68 + oc + 8] = fmaf(acc[mi][ni][3], sc1, sh1);
                }
            }
        }
        __syncthreads();
        // cooperative coalesced store of the 128t x 64o half
#pragma unroll
        for (int i = 0; i < 8; i++) {
            int idx = tid + 256 * i;        // 0..2047
            int o4  = idx & 15;
            int t   = idx >> 4;
            float4 v = *(const float4*)(se + t * 68 + o4 * 4);
            *(float4*)(g_y + ((size_t)(b * TLEN + tBase + t)) * COUT
                       + oBase + h * 64 + o4 * 4) = v;
        }
    }
}

// ============================================================================
// Kernel 2: LIF recurrence + time-mean, 4-deep chunk pipeline (48 loads live).
// ============================================================================
__global__ __launch_bounds__(128) void lif_kernel(float* __restrict__ out)
{
    const int idx = blockIdx.x * 128 + threadIdx.x;   // 0..16383
    const int b = idx >> 8;
    const int o = idx & 255;
    const float* p = g_y + (size_t)b * TLEN * COUT + o;

    float B0[16], B1[16], B2[16], B3[16];
    float v = 0.0f, sum = 0.0f;

#define LOADC(BUF, c) do {                                                    \
    const float* _q = p + (size_t)(c) * 16 * COUT;                            \
    _Pragma("unroll")                                                         \
    for (int j = 0; j < 16; j++) BUF[j] = _q[(size_t)j * COUT];               \
} while (0)
#define PROC(BUF) do {                                                        \
    _Pragma("unroll")                                                         \
    for (int j = 0; j < 16; j++) {                                            \
        float u = v + (BUF[j] - v) * 0.5f;   /* exact: (y-v)/TAU, TAU=2 */    \
        bool sp = (u >= 1.0f);                                                \
        sum += sp ? 1.0f : 0.0f;                                              \
        v = sp ? 0.0f : u;                                                    \
    }                                                                         \
} while (0)

    LOADC(B0, 0); LOADC(B1, 1); LOADC(B2, 2);
#pragma unroll 1
    for (int i = 0; i < 60; i += 4) {
        LOADC(B3, i + 3); PROC(B0);
        LOADC(B0, i + 4); PROC(B1);
        LOADC(B1, i + 5); PROC(B2);
        LOADC(B2, i + 6); PROC(B3);
    }
    LOADC(B3, 63);
    PROC(B0); PROC(B1); PROC(B2); PROC(B3);

    out[idx] = sum * (1.0f / 1024.0f);
#undef LOADC
#undef PROC
}

// ============================================================================
extern "C" void kernel_launch(void* const* d_in, const int* in_sizes, int n_in,
                              void* d_out, int out_size)
{
    const float* x     = (const float*)d_in[0];
    const float* W     = (const float*)d_in[1];
    const float* gamma = (const float*)d_in[2];
    const float* beta  = (const float*)d_in[3];
    const float* rmean = (const float*)d_in[4];
    const float* rvar  = (const float*)d_in[5];
    float* out = (float*)d_out;

    cudaFuncSetAttribute(gemm_mma_kernel,
                         cudaFuncAttributeMaxDynamicSharedMemorySize, DSMB);

    wprep_kernel<<<384, 256>>>(W);

    dim3 g1(TLEN / 128, COUT / 128, BATCH);   // 8 x 2 x 64 = 1024 blocks
    gemm_mma_kernel<<<g1, 256, DSMB>>>(x, gamma, beta, rmean, rvar);

    lif_kernel<<<(BATCH * COUT) / 128, 128>>>(out);
}